// round 14
// baseline (speedup 1.0000x reference)
#include <cuda_runtime.h>
#include <cstdint>

#define TSTEPS 1024
#define BATCH  256
#define INSZ   128
#define HID    512
#define OUTSZ  32
#define RB     16      // batch rows per cluster
#define JT     64      // hidden outputs per CTA
#define CLUSZ  8       // CTAs per cluster
#define THR2   1024    // threads per rnn CTA (32 warps)
#define HPAD   520     // padded raw h row

// scratch (device globals: the sanctioned no-alloc workaround)
__device__ float g_xproj[(size_t)TSTEPS * BATCH * HID];   // 512 MB
__device__ float g_h[2][BATCH * HID];                     // double-buffered state

// ---------------- packed f32x2 helpers ----------------
__device__ __forceinline__ void fma2(unsigned long long& d,
                                     unsigned long long a,
                                     unsigned long long b) {
    asm("fma.rn.f32x2 %0, %1, %2, %0;" : "+l"(d) : "l"(a), "l"(b));
}
__device__ __forceinline__ unsigned long long splat2(float a) {
    unsigned long long r;
    asm("mov.b64 %0, {%1, %1};" : "=l"(r) : "f"(a));
    return r;
}
__device__ __forceinline__ unsigned long long pk2(float x, float y) {
    unsigned long long r;
    asm("mov.b64 %0, {%1, %2};" : "=l"(r) : "f"(x), "f"(y));
    return r;
}
__device__ __forceinline__ float2 unpk(unsigned long long v) {
    float2 f;
    asm("mov.b64 {%0, %1}, %2;" : "=f"(f.x), "=f"(f.y) : "l"(v));
    return f;
}
__device__ __forceinline__ uint32_t smem_u32(const void* p) {
    uint32_t a;
    asm("{ .reg .u64 t; cvta.to.shared.u64 t, %1; cvt.u32.u64 %0, t; }"
        : "=r"(a) : "l"(p));
    return a;
}
__device__ __forceinline__ void cp16_cg(uint32_t dst_smem, const void* src) {
    asm volatile("cp.async.cg.shared.global [%0], [%1], 16;"
                 :: "r"(dst_smem), "l"(src) : "memory");
}
__device__ __forceinline__ void cp_commit() {
    asm volatile("cp.async.commit_group;" ::: "memory");
}
__device__ __forceinline__ void cp_wait_all() {
    asm volatile("cp.async.wait_group 0;" ::: "memory");
}
// ---------------- tf32 mma helpers ----------------
__device__ __forceinline__ uint32_t to_tf32(float f) {
    uint32_t u;
    asm("cvt.rna.tf32.f32 %0, %1;" : "=r"(u) : "f"(f));
    return u;
}
__device__ __forceinline__ void mma_tf32(float& c0, float& c1, float& c2, float& c3,
                                         uint32_t a0, uint32_t a1, uint32_t a2, uint32_t a3,
                                         uint32_t b0, uint32_t b1) {
    asm volatile("mma.sync.aligned.m16n8k8.row.col.f32.tf32.tf32.f32 "
                 "{%0,%1,%2,%3}, {%4,%5,%6,%7}, {%8,%9}, {%0,%1,%2,%3};"
                 : "+f"(c0), "+f"(c1), "+f"(c2), "+f"(c3)
                 : "r"(a0), "r"(a1), "r"(a2), "r"(a3), "r"(b0), "r"(b1));
}

// ---------------------------------------------------------------------------
// Kernel 1: x_proj[t,b,:] = inputs[t,b,:] @ W_in + b_rec
// ---------------------------------------------------------------------------
__global__ void __launch_bounds__(256, 1)
xproj_kernel(const float* __restrict__ in, const float* __restrict__ Win,
             const float* __restrict__ brec)
{
    extern __shared__ float sm1[];
    float*  As  = sm1;               // [128][132] padded
    float4* As4 = (float4*)As;
    float*  Bs  = sm1 + 128 * 132;   // [128][128]
    float4* Bs4 = (float4*)Bs;

    const int tid = threadIdx.x;
    const int m0  = blockIdx.x * 128;
    const int n0  = blockIdx.y * 128;

    for (int i = tid; i < 4096; i += 256) {
        int m = i >> 5, kq = i & 31;
        As4[m * 33 + kq] = *(const float4*)(in + (size_t)(m0 + m) * INSZ + kq * 4);
    }
    for (int i = tid; i < 4096; i += 256) {
        int k = i >> 5, nq = i & 31;
        Bs4[k * 32 + nq] = *(const float4*)(Win + (size_t)k * HID + n0 + nq * 4);
    }
    __syncthreads();

    const int tx = tid & 15, ty = tid >> 4;
    const int mm = ty * 8,   nn = tx * 8;

    unsigned long long accq[8][4];
#pragma unroll
    for (int i = 0; i < 8; i++)
#pragma unroll
        for (int jj = 0; jj < 4; jj++) accq[i][jj] = 0ULL;

#pragma unroll 4
    for (int k = 0; k < 128; k++) {
        unsigned long long aa[8];
#pragma unroll
        for (int i = 0; i < 8; i++) aa[i] = splat2(As[(mm + i) * 132 + k]);
        const ulonglong2* bq = (const ulonglong2*)(Bs4 + k * 32 + (nn >> 2));
        ulonglong2 bA = bq[0];
        ulonglong2 bB = bq[1];
#pragma unroll
        for (int i = 0; i < 8; i++) {
            fma2(accq[i][0], aa[i], bA.x);
            fma2(accq[i][1], aa[i], bA.y);
            fma2(accq[i][2], aa[i], bB.x);
            fma2(accq[i][3], aa[i], bB.y);
        }
    }

    float4 br0 = *(const float4*)(brec + n0 + nn);
    float4 br1 = *(const float4*)(brec + n0 + nn + 4);
#pragma unroll
    for (int i = 0; i < 8; i++) {
        float2 p0 = unpk(accq[i][0]), p1 = unpk(accq[i][1]);
        float2 p2 = unpk(accq[i][2]), p3 = unpk(accq[i][3]);
        float4 s0 = make_float4(p0.x + br0.x, p0.y + br0.y, p1.x + br0.z, p1.y + br0.w);
        float4 s1 = make_float4(p2.x + br1.x, p2.y + br1.y, p3.x + br1.z, p3.y + br1.w);
        float* dst = g_xproj + (size_t)(m0 + mm + i) * HID + n0 + nn;
        *(float4*)dst       = s0;
        *(float4*)(dst + 4) = s1;
    }
}

// ---------------------------------------------------------------------------
// Kernel 2: persistent recurrence, tf32 mma.sync + frag-major smem staging.
// ---------------------------------------------------------------------------
// smem layout (float offsets)
#define SM_RAW0  0                     // [16][520]   raw H, buffer 0
#define SM_RAW1  8320                  // [16][520]   raw H, buffer 1
#define SM_FRAG  16640                 // tf32 frags [4][16][32] x uint4 = 8192
#define SM_PART  24832                 // [4][16][64] 4096
#define SM_OPART 28928                 // [16][64]    1024
#define SM_XP    29952                 // [2][16][64] 2048
#define SM_WPK   32000                 // wpack [256][32] float2 = 16384
#define SM_BOUT  48384                 // [32]
#define SM2_BYTES ((48384 + 32 + 16) * 4)

// scatter one float4 of H (element index i in [0,2048)) into tf32 frag buffer
__device__ __forceinline__ void frag_store(uint32_t* fragb, int i, float4 hv) {
    const int b     = i >> 7;
    const int kfour = (i & 127) * 4;
    const int kq_   = kfour >> 7;
    const int kk_   = (kfour >> 3) & 15;
    const int slot  = ((kfour & 4) ? 2 : 0) + ((b >= 8) ? 1 : 0);
    const int lanev = (b & 7) * 4;
    const int sw    = kk_ & 7;
    const uint32_t base = (uint32_t)((kq_ * 16 + kk_) * 32);
    fragb[(base + ((lanev + 0) ^ sw)) * 4 + slot] = to_tf32(hv.x);
    fragb[(base + ((lanev + 1) ^ sw)) * 4 + slot] = to_tf32(hv.y);
    fragb[(base + ((lanev + 2) ^ sw)) * 4 + slot] = to_tf32(hv.z);
    fragb[(base + ((lanev + 3) ^ sw)) * 4 + slot] = to_tf32(hv.w);
}

// oproj partial: f32x2 over 32 k-values; ro = raw row base (orow*HPAD)
__device__ __forceinline__ void oproj_acc(const float* ro,
                                          const unsigned long long* wpu,
                                          float* sh_opart, int oo, int oks, int tid) {
    const float4* ro4 = (const float4*)(ro + oks * 32);
    const unsigned long long* wp = wpu + (size_t)oks * 16 * 32 + oo;
    unsigned long long acc0 = 0ULL, acc1 = 0ULL;
#pragma unroll
    for (int k4 = 0; k4 < 8; k4++) {
        float4 hv = ro4[k4];
        fma2(acc0, pk2(hv.x, hv.y), wp[(k4 * 2    ) * 32]);
        fma2(acc1, pk2(hv.z, hv.w), wp[(k4 * 2 + 1) * 32]);
    }
    float2 u = unpk(acc0), v = unpk(acc1);
    sh_opart[oks * 64 + (tid & 63)] = (u.x + u.y) + (v.x + v.y);
}

__global__ void __cluster_dims__(CLUSZ, 1, 1) __launch_bounds__(THR2, 1)
rnn_kernel(const float* __restrict__ Wrec, const float* __restrict__ Wout,
           const float* __restrict__ bout, float* __restrict__ out)
{
    extern __shared__ float sm[];
    float*     sh_raw   = sm + SM_RAW0;          // two buffers, 8320 apart
    uint32_t*  sh_frag  = (uint32_t*)(sm + SM_FRAG);
    float*     sh_part  = sm + SM_PART;
    float*     sh_opart = sm + SM_OPART;
    float*     sh_xp    = sm + SM_XP;
    unsigned long long* sh_wpk = (unsigned long long*)(sm + SM_WPK);
    float*     sh_bout  = sm + SM_BOUT;

    const int tid   = threadIdx.x;
    const int lane  = tid & 31;
    const int warp  = tid >> 5;
    const int noct  = warp & 7;
    const int kq    = warp >> 3;
    const int rank  = blockIdx.x & (CLUSZ - 1);
    const int clu   = blockIdx.x >> 3;
    const int b0    = clu * RB;
    const int jbase = rank * JT;

    // ---- B fragments: W^T, tf32, resident (32 regs) ----
    uint32_t Bf[16][2];
    {
        const int n   = lane >> 2;
        const int kk0 = lane & 3;
        const float* wr = Wrec + (size_t)(jbase + noct * 8 + n) * HID + kq * 128 + kk0;
#pragma unroll
        for (int kk = 0; kk < 16; kk++) {
            Bf[kk][0] = to_tf32(wr[kk * 8]);
            Bf[kk][1] = to_tf32(wr[kk * 8 + 4]);
        }
    }
    // ---- wpack: (W_out[2k][o], W_out[2k+1][o]) pairs; b_out ----
    for (int idx = tid; idx < 256 * 32; idx += THR2) {
        int k2 = idx >> 5, oo_ = idx & 31;
        ((float2*)sh_wpk)[idx] =
            make_float2(Wout[(2 * k2) * OUTSZ + oo_], Wout[(2 * k2 + 1) * OUTSZ + oo_]);
    }
    if (tid < OUTSZ) sh_bout[tid] = bout[tid];

    // zero raw buffer 0 (H_0 = 0) and frag buffer (MMA at s=0 gives 0)
    for (int i = tid; i < 8320; i += THR2) sh_raw[i] = 0.f;
    for (int i = tid; i < 8192; i += THR2) sh_frag[i] = 0u;

    // xp prefetch geometry
    const int xb = tid >> 4, xq = tid & 15;
    const float* xsrc0 = g_xproj + (size_t)(b0 + xb) * HID + jbase + xq * 4;
    const uint32_t xp_smem0 = smem_u32(sh_xp) + (uint32_t)(xb * 64 + xq * 4) * 4;
    if (tid < 256) cp16_cg(xp_smem0, xsrc0);
    cp_commit();

    // oproj mapping
    const int oo   = tid & 31;
    const int orow = 2 * rank + ((tid >> 5) & 1);
    const int oks  = tid >> 6;

    for (int s = 0; s < TSTEPS; ++s) {
        float* raw_cur = sh_raw + (s & 1) * 8320;
        // ---- issue H_s loads early (latency covered by oproj below) ----
        float4 hr0, hr1;
        if (s > 0) {
            const float4* hs = (const float4*)(g_h[s & 1] + (size_t)b0 * HID);
            hr0 = __ldcv(hs + tid);
            hr1 = __ldcv(hs + tid + THR2);
        }
        // ---- output projection accumulate for step s-2 (old raw buffer) ----
        if (s >= 2)
            oproj_acc(sh_raw + ((s - 1) & 1) * 8320 + orow * HPAD,
                      sh_wpk, sh_opart, oo, oks, tid);
        // ---- store H_s: raw (float4) + tf32 frag scatter ----
        if (s > 0) {
            float4* raw4 = (float4*)raw_cur;
            const int b0i = tid >> 7,          c0i = tid & 127;
            const int b1i = (tid + THR2) >> 7, c1i = (tid + THR2) & 127;
            raw4[b0i * (HPAD / 4) + c0i] = hr0;
            raw4[b1i * (HPAD / 4) + c1i] = hr1;
            frag_store(sh_frag, tid, hr0);
            frag_store(sh_frag, tid + THR2, hr1);
        }
        cp_wait_all();          // xp(s) ready in buffer s&1
        __syncthreads();        // sync1

        // prefetch xp(s+1)
        if (s + 1 < TSTEPS && tid < 256)
            cp16_cg(xp_smem0 + ((s + 1) & 1) * 4096,
                    xsrc0 + (size_t)(s + 1) * BATCH * HID);
        cp_commit();

        // ---- recurrent matmul: 16 tf32 MMAs from frag buffer ----
        {
            float c0 = 0.f, c1 = 0.f, c2 = 0.f, c3 = 0.f;
            const uint4* fr = (const uint4*)sh_frag;
#pragma unroll
            for (int kk = 0; kk < 16; kk++) {
                uint4 af = fr[(kq * 16 + kk) * 32 + (lane ^ (kk & 7))];
                mma_tf32(c0, c1, c2, c3, af.x, af.y, af.z, af.w, Bf[kk][0], Bf[kk][1]);
            }
            const int bb = lane >> 2;
            const int jj = noct * 8 + (lane & 3) * 2;
            *(float2*)&sh_part[(kq * 16 + bb    ) * 64 + jj] = make_float2(c0, c1);
            *(float2*)&sh_part[(kq * 16 + bb + 8) * 64 + jj] = make_float2(c2, c3);
        }
        // ---- oproj finalize for step s-2 ----
        if (s >= 2 && tid < 64) {
            float v = sh_bout[tid & 31];
#pragma unroll
            for (int k = 0; k < 16; k++) v += sh_opart[k * 64 + tid];
            int row = b0 + 2 * rank + (tid >> 5);
            out[((size_t)(s - 2) * BATCH + row) * OUTSZ + (tid & 31)] = v;
        }
        __syncthreads();        // sync2

        // ---- state update: one (b,j) element per thread ----
        {
            const int b = tid >> 6, j = tid & 63;
            float pre = (sh_part[(b     ) * 64 + j] + sh_part[(16 + b) * 64 + j])
                      + (sh_part[(32 + b) * 64 + j] + sh_part[(48 + b) * 64 + j]);
            const float* xp_cur = sh_xp + (s & 1) * 1024;
            float act = pre + xp_cur[b * 64 + j];
            act = act > 0.f ? act : 0.f;
            float hn = 0.999f * raw_cur[b * HPAD + jbase + j] + 0.001f * act;
            g_h[(s + 1) & 1][(size_t)(b0 + b) * HID + jbase + j] = hn;
        }
        // cluster barrier (release/acquire publishes g_h; peers use __ldcv)
        asm volatile("barrier.cluster.arrive.aligned;" ::: "memory");
        asm volatile("barrier.cluster.wait.aligned;"   ::: "memory");
    }

    // ---- epilogue A: out[1022] from H_1023 (raw buffer 1) ----
    oproj_acc(sh_raw + 8320 + orow * HPAD, sh_wpk, sh_opart, oo, oks, tid);
    __syncthreads();
    if (tid < 64) {
        float v = sh_bout[tid & 31];
#pragma unroll
        for (int k = 0; k < 16; k++) v += sh_opart[k * 64 + tid];
        int row = b0 + 2 * rank + (tid >> 5);
        out[((size_t)1022 * BATCH + row) * OUTSZ + (tid & 31)] = v;
    }
    // load H_1024 (g_h[0]) into raw buffer 0
    {
        const float4* hs = (const float4*)(g_h[0] + (size_t)b0 * HID);
        float4* raw4 = (float4*)sh_raw;
        raw4[(tid >> 7) * (HPAD / 4) + (tid & 127)] = __ldcv(hs + tid);
        raw4[((tid + THR2) >> 7) * (HPAD / 4) + ((tid + THR2) & 127)] =
            __ldcv(hs + tid + THR2);
    }
    __syncthreads();
    // ---- epilogue B: out[1023] from H_1024 ----
    oproj_acc(sh_raw + orow * HPAD, sh_wpk, sh_opart, oo, oks, tid);
    __syncthreads();
    if (tid < 64) {
        float v = sh_bout[tid & 31];
#pragma unroll
        for (int k = 0; k < 16; k++) v += sh_opart[k * 64 + tid];
        int row = b0 + 2 * rank + (tid >> 5);
        out[((size_t)1023 * BATCH + row) * OUTSZ + (tid & 31)] = v;
    }
}

// ---------------------------------------------------------------------------
extern "C" void kernel_launch(void* const* d_in, const int* in_sizes, int n_in,
                              void* d_out, int out_size)
{
    const float* inputs = (const float*)d_in[0];
    const float* Wrec   = (const float*)d_in[1];
    const float* Win    = (const float*)d_in[2];
    const float* brec   = (const float*)d_in[3];
    const float* Wout   = (const float*)d_in[4];
    const float* bout   = (const float*)d_in[5];
    float* out = (float*)d_out;

    const int smem1 = (128 * 132 + 128 * 128) * 4;   // 133120
    cudaFuncSetAttribute(xproj_kernel, cudaFuncAttributeMaxDynamicSharedMemorySize, smem1);
    cudaFuncSetAttribute(rnn_kernel,   cudaFuncAttributeMaxDynamicSharedMemorySize, SM2_BYTES);

    dim3 g1((TSTEPS * BATCH) / 128, HID / 128);
    xproj_kernel<<<g1, 256, smem1>>>(inputs, Win, brec);

    rnn_kernel<<<128, THR2, SM2_BYTES>>>(Wrec, Wout, bout, out);

    (void)in_sizes; (void)n_in; (void)out_size;
}

// round 15
// speedup vs baseline: 1.3573x; 1.3573x over previous
#include <cuda_runtime.h>
#include <cstdint>

#define TSTEPS 1024
#define BATCH  256
#define INSZ   128
#define HID    512
#define OUTSZ  32
#define RB     16      // batch rows per cluster
#define JT     64      // hidden outputs per CTA
#define CLUSZ  8       // CTAs per cluster
#define THR2   512     // threads per rnn CTA (16 warps)
#define HROW   516     // padded tf32 H row (516 mod 32 = 4 -> conflict-free)

// scratch (device globals: the sanctioned no-alloc workaround)
__device__ float g_xproj[(size_t)TSTEPS * BATCH * HID];   // 512 MB
__device__ float g_hist[(size_t)TSTEPS * BATCH * HID];    // 512 MB: h_t for all t

// ---------------- packed f32x2 helpers ----------------
__device__ __forceinline__ void fma2(unsigned long long& d,
                                     unsigned long long a,
                                     unsigned long long b) {
    asm("fma.rn.f32x2 %0, %1, %2, %0;" : "+l"(d) : "l"(a), "l"(b));
}
__device__ __forceinline__ unsigned long long splat2(float a) {
    unsigned long long r;
    asm("mov.b64 %0, {%1, %1};" : "=l"(r) : "f"(a));
    return r;
}
__device__ __forceinline__ unsigned long long pk2(float x, float y) {
    unsigned long long r;
    asm("mov.b64 %0, {%1, %2};" : "=l"(r) : "f"(x), "f"(y));
    return r;
}
__device__ __forceinline__ float2 unpk(unsigned long long v) {
    float2 f;
    asm("mov.b64 {%0, %1}, %2;" : "=f"(f.x), "=f"(f.y) : "l"(v));
    return f;
}
__device__ __forceinline__ uint32_t smem_u32(const void* p) {
    uint32_t a;
    asm("{ .reg .u64 t; cvta.to.shared.u64 t, %1; cvt.u32.u64 %0, t; }"
        : "=r"(a) : "l"(p));
    return a;
}
__device__ __forceinline__ void cp16_cg(uint32_t dst_smem, const void* src) {
    asm volatile("cp.async.cg.shared.global [%0], [%1], 16;"
                 :: "r"(dst_smem), "l"(src) : "memory");
}
__device__ __forceinline__ void cp_commit() {
    asm volatile("cp.async.commit_group;" ::: "memory");
}
__device__ __forceinline__ void cp_wait_all() {
    asm volatile("cp.async.wait_group 0;" ::: "memory");
}
// ---------------- tf32 mma helpers ----------------
__device__ __forceinline__ uint32_t to_tf32(float f) {
    uint32_t u;
    asm("cvt.rna.tf32.f32 %0, %1;" : "=r"(u) : "f"(f));
    return u;
}
__device__ __forceinline__ void mma_tf32(float& c0, float& c1, float& c2, float& c3,
                                         uint32_t a0, uint32_t a1, uint32_t a2, uint32_t a3,
                                         uint32_t b0, uint32_t b1) {
    asm volatile("mma.sync.aligned.m16n8k8.row.col.f32.tf32.tf32.f32 "
                 "{%0,%1,%2,%3}, {%4,%5,%6,%7}, {%8,%9}, {%0,%1,%2,%3};"
                 : "+f"(c0), "+f"(c1), "+f"(c2), "+f"(c3)
                 : "r"(a0), "r"(a1), "r"(a2), "r"(a3), "r"(b0), "r"(b1));
}

// ---------------------------------------------------------------------------
// Kernel 1: x_proj[t,b,:] = inputs[t,b,:] @ W_in + b_rec
// ---------------------------------------------------------------------------
__global__ void __launch_bounds__(256, 1)
xproj_kernel(const float* __restrict__ in, const float* __restrict__ Win,
             const float* __restrict__ brec)
{
    extern __shared__ float sm1[];
    float*  As  = sm1;               // [128][132] padded
    float4* As4 = (float4*)As;
    float*  Bs  = sm1 + 128 * 132;   // [128][128]
    float4* Bs4 = (float4*)Bs;

    const int tid = threadIdx.x;
    const int m0  = blockIdx.x * 128;
    const int n0  = blockIdx.y * 128;

    for (int i = tid; i < 4096; i += 256) {
        int m = i >> 5, kq = i & 31;
        As4[m * 33 + kq] = *(const float4*)(in + (size_t)(m0 + m) * INSZ + kq * 4);
    }
    for (int i = tid; i < 4096; i += 256) {
        int k = i >> 5, nq = i & 31;
        Bs4[k * 32 + nq] = *(const float4*)(Win + (size_t)k * HID + n0 + nq * 4);
    }
    __syncthreads();

    const int tx = tid & 15, ty = tid >> 4;
    const int mm = ty * 8,   nn = tx * 8;

    unsigned long long accq[8][4];
#pragma unroll
    for (int i = 0; i < 8; i++)
#pragma unroll
        for (int jj = 0; jj < 4; jj++) accq[i][jj] = 0ULL;

#pragma unroll 4
    for (int k = 0; k < 128; k++) {
        unsigned long long aa[8];
#pragma unroll
        for (int i = 0; i < 8; i++) aa[i] = splat2(As[(mm + i) * 132 + k]);
        const ulonglong2* bq = (const ulonglong2*)(Bs4 + k * 32 + (nn >> 2));
        ulonglong2 bA = bq[0];
        ulonglong2 bB = bq[1];
#pragma unroll
        for (int i = 0; i < 8; i++) {
            fma2(accq[i][0], aa[i], bA.x);
            fma2(accq[i][1], aa[i], bA.y);
            fma2(accq[i][2], aa[i], bB.x);
            fma2(accq[i][3], aa[i], bB.y);
        }
    }

    float4 br0 = *(const float4*)(brec + n0 + nn);
    float4 br1 = *(const float4*)(brec + n0 + nn + 4);
#pragma unroll
    for (int i = 0; i < 8; i++) {
        float2 p0 = unpk(accq[i][0]), p1 = unpk(accq[i][1]);
        float2 p2 = unpk(accq[i][2]), p3 = unpk(accq[i][3]);
        float4 s0 = make_float4(p0.x + br0.x, p0.y + br0.y, p1.x + br0.z, p1.y + br0.w);
        float4 s1 = make_float4(p2.x + br1.x, p2.y + br1.y, p3.x + br1.z, p3.y + br1.w);
        float* dst = g_xproj + (size_t)(m0 + mm + i) * HID + n0 + nn;
        *(float4*)dst       = s0;
        *(float4*)(dst + 4) = s1;
    }
}

// ---------------------------------------------------------------------------
// Kernel 2: persistent recurrence only (no oproj). 512 threads, 16 warps.
// grid = 128 CTAs = 16 clusters x 8; cluster c owns batch rows [16c,16c+16);
// CTA rank r owns hidden slice [64r, 64r+64).
// Warp w = (nh = w&1, ks = w>>1): n-half (32 j) x k-segment (64 k).
// B-frags: 64 regs tf32 (8 kk x 4 nsub x 2). A from tf32 smem H (pad 516).
// Each thread keeps its 2 state elements in registers; h published via
// g_hist[s] (doubles as the history for the final output GEMM).
// ---------------------------------------------------------------------------
#define SM_HA    0                     // tf32 H: [16][516] = 8256 words
#define SM_PART  8256                  // [8][16][64] = 8192
#define SM_XP    16448                 // [2][16][64] = 2048
#define SM2_WORDS (16448 + 2048 + 16)
#define SM2_BYTES (SM2_WORDS * 4)

__global__ void __cluster_dims__(CLUSZ, 1, 1) __launch_bounds__(THR2, 1)
rnn_kernel(const float* __restrict__ Wrec)
{
    extern __shared__ float sm[];
    uint32_t* hA      = (uint32_t*)(sm + SM_HA);
    float*    sh_part = sm + SM_PART;
    float*    sh_xp   = sm + SM_XP;

    const int tid   = threadIdx.x;
    const int lane  = tid & 31;
    const int warp  = tid >> 5;
    const int nh    = warp & 1;          // n-half (32 j)
    const int ks    = warp >> 1;         // k-segment (64 k)
    const int rank  = blockIdx.x & (CLUSZ - 1);
    const int clu   = blockIdx.x >> 3;
    const int b0    = clu * RB;
    const int jbase = rank * JT;

    // ---- B fragments: W^T, tf32, resident (64 regs) ----
    uint32_t Bf[8][4][2];
    {
        const int n4 = lane >> 2;        // n within octet
        const int k4 = lane & 3;         // k within 4
#pragma unroll
        for (int nsub = 0; nsub < 4; nsub++) {
            const float* wr = Wrec
                + (size_t)(jbase + nh * 32 + nsub * 8 + n4) * HID + ks * 64 + k4;
#pragma unroll
            for (int kk = 0; kk < 8; kk++) {
                Bf[kk][nsub][0] = to_tf32(wr[kk * 8]);
                Bf[kk][nsub][1] = to_tf32(wr[kk * 8 + 4]);
            }
        }
    }

    // zero tf32 H (H_0 = 0)
    for (int i = tid; i < 16 * HROW; i += THR2) hA[i] = 0u;

    // resident state: this thread owns elements (b,j) for idx = tid, tid+512
    float h_own[2] = {0.f, 0.f};

    // xp prefetch geometry: 256 threads each copy one float4 of [16][64]
    const int xb = tid >> 4, xq = tid & 15;
    const float* xsrc0 = g_xproj + (size_t)(b0 + xb) * HID + jbase + xq * 4;
    const uint32_t xp_smem0 = smem_u32(sh_xp) + (uint32_t)(xb * 64 + xq * 4) * 4;
    if (tid < 256) cp16_cg(xp_smem0, xsrc0);
    cp_commit();

    for (int s = 0; s < TSTEPS; ++s) {
        // ---- stage H_s into tf32 smem (s>0: read peers' g_hist[s-1]) ----
        if (s > 0) {
            const float4* hs =
                (const float4*)(g_hist + ((size_t)(s - 1) * BATCH + b0) * HID);
#pragma unroll
            for (int u = 0; u < 4; u++) {
                const int i   = tid + THR2 * u;      // 0..2047 float4 index
                float4 hv = __ldcv(hs + i);
                const int row = i >> 7;
                const int c4  = (i & 127) * 4;
                uint4 tv = make_uint4(to_tf32(hv.x), to_tf32(hv.y),
                                      to_tf32(hv.z), to_tf32(hv.w));
                *(uint4*)(hA + row * HROW + c4) = tv;
            }
        }
        cp_wait_all();            // xp(s) ready in buffer s&1
        __syncthreads();          // sync1: hA + xp visible

        // prefetch xp(s+1)
        if (s + 1 < TSTEPS && tid < 256)
            cp16_cg(xp_smem0 + ((s + 1) & 1) * 4096,
                    xsrc0 + (size_t)(s + 1) * BATCH * HID);
        cp_commit();

        // ---- recurrent matmul: 8 kk x 4 nsub m16n8k8 tf32 MMAs ----
        {
            float c0[4], c1[4], c2[4], c3[4];
#pragma unroll
            for (int n = 0; n < 4; n++) { c0[n]=0.f; c1[n]=0.f; c2[n]=0.f; c3[n]=0.f; }
            const int r4   = lane >> 2;
            const int k4   = lane & 3;
            const uint32_t* ap = hA + r4 * HROW + ks * 64 + k4;
#pragma unroll
            for (int kk = 0; kk < 8; kk++) {
                uint32_t a0 = ap[kk * 8];
                uint32_t a1 = ap[kk * 8 + 8 * HROW];
                uint32_t a2 = ap[kk * 8 + 4];
                uint32_t a3 = ap[kk * 8 + 8 * HROW + 4];
#pragma unroll
                for (int n = 0; n < 4; n++)
                    mma_tf32(c0[n], c1[n], c2[n], c3[n],
                             a0, a1, a2, a3, Bf[kk][n][0], Bf[kk][n][1]);
            }
            const int bb = lane >> 2;
            const int jj = nh * 32 + (lane & 3) * 2;
#pragma unroll
            for (int n = 0; n < 4; n++) {
                *(float2*)&sh_part[(ks * 16 + bb    ) * 64 + jj + n * 8] =
                    make_float2(c0[n], c1[n]);
                *(float2*)&sh_part[(ks * 16 + bb + 8) * 64 + jj + n * 8] =
                    make_float2(c2[n], c3[n]);
            }
        }
        __syncthreads();          // sync2: partials ready

        // ---- state update: 2 elements per thread, state in registers ----
        {
            const float* xp_cur = sh_xp + (s & 1) * 1024;
            float* gdst = g_hist + ((size_t)s * BATCH + b0) * HID;
#pragma unroll
            for (int u = 0; u < 2; u++) {
                const int idx = tid + THR2 * u;
                const int b = idx >> 6, j = idx & 63;
                float pre = 0.f;
#pragma unroll
                for (int k = 0; k < 8; k++)
                    pre += sh_part[(k * 16 + b) * 64 + j];
                float act = pre + xp_cur[b * 64 + j];
                act = act > 0.f ? act : 0.f;
                float hn = 0.999f * h_own[u] + 0.001f * act;
                h_own[u] = hn;
                gdst[(size_t)b * HID + jbase + j] = hn;
            }
        }
        // cluster barrier: arrive(release) publishes g_hist stores;
        // wait(acquire) + __ldcv on the peer side makes them visible.
        asm volatile("barrier.cluster.arrive.aligned;" ::: "memory");
        asm volatile("barrier.cluster.wait.aligned;"   ::: "memory");
    }
}

// ---------------------------------------------------------------------------
// Kernel 3: out[t,b,:] = g_hist[t,b,:] @ W_out + b_out   (M=262144,K=512,N=32)
// ---------------------------------------------------------------------------
#define OG_AS    0                         // [128][132] = 16896 words
#define OG_WPK   16896                     // wpack [256][32] float2 = 16384 words
#define OG_BOUT  (16896 + 16384)           // [32]
#define OG_BYTES ((OG_BOUT + 32 + 16) * 4)

__global__ void __launch_bounds__(256, 1)
ogemm_kernel(const float* __restrict__ Wout, const float* __restrict__ bout,
             float* __restrict__ out)
{
    extern __shared__ float smo[];
    float* As = smo + OG_AS;                       // [128][132]
    unsigned long long* wpk = (unsigned long long*)(smo + OG_WPK);
    float* sbout = smo + OG_BOUT;

    const int tid = threadIdx.x;
    const size_t m0 = (size_t)blockIdx.x * 128;

    // wpack: (W_out[2k][o], W_out[2k+1][o]) pairs
    for (int idx = tid; idx < 256 * 32; idx += 256) {
        int k2 = idx >> 5, oo = idx & 31;
        ((float2*)wpk)[idx] =
            make_float2(Wout[(2 * k2) * OUTSZ + oo], Wout[(2 * k2 + 1) * OUTSZ + oo]);
    }
    if (tid < OUTSZ) sbout[tid] = bout[tid];

    const int r    = tid >> 1;         // row 0..127
    const int half = tid & 1;          // 16-col half

    unsigned long long acc[8];
#pragma unroll
    for (int c = 0; c < 8; c++) acc[c] = 0ULL;

    for (int kc = 0; kc < 4; kc++) {
        __syncthreads();
        // load A chunk [128][128] from g_hist
#pragma unroll
        for (int u = 0; u < 16; u++) {
            int i = tid + 256 * u;                 // 0..4095 float4
            int row = i >> 5, c4 = (i & 31) * 4;
            *(float4*)&As[row * 132 + c4] =
                *(const float4*)(g_hist + (m0 + row) * HID + kc * 128 + c4);
        }
        __syncthreads();

        const unsigned long long* wp = wpk + (size_t)kc * 64 * 32 + half * 16;
        const float* ar = As + r * 132;
#pragma unroll 8
        for (int k2 = 0; k2 < 64; k2++) {
            unsigned long long hp = pk2(ar[2 * k2], ar[2 * k2 + 1]);
            const unsigned long long* w = wp + (size_t)k2 * 32;
#pragma unroll
            for (int c = 0; c < 8; c++) fma2(acc[c], hp, w[c * 2]);
        }
    }

    // write 16 outputs
    float* dst = out + (m0 + r) * OUTSZ + half * 16;
#pragma unroll
    for (int c = 0; c < 8; c++) {
        float2 u = unpk(acc[c]);
        // acc[c] pairs correspond to cols half*16 + 2c, 2c+1
        dst[2 * c]     = u.x + u.y - u.y;  // placeholder fixed below
        (void)u;
    }
    // NOTE: correct unpack: out[col] = lo + hi of acc for that col
#pragma unroll
    for (int c = 0; c < 8; c++) {
        float2 u = unpk(acc[c]);
        int col0 = half * 16 + 2 * c;
        // wpk pair c*2 covers cols (half*16 + 2c) and +1? No: w[c*2] is col
        // offset 2c within the half -> acc[c] accumulates a SINGLE col pair:
        // lo += h_even*W[2k][col], hi += h_odd*W[2k+1][col], col = half*16+2c.
        out[(m0 + r) * OUTSZ + col0] = u.x + u.y + sbout[col0];
        (void)col0;
    }
    // cols half*16 + odd (2c+1): second pass with w offset +1
    {
        unsigned long long acc2[8];
#pragma unroll
        for (int c = 0; c < 8; c++) acc2[c] = 0ULL;
        for (int kc = 0; kc < 4; kc++) {
            __syncthreads();
#pragma unroll
            for (int u = 0; u < 16; u++) {
                int i = tid + 256 * u;
                int row = i >> 5, c4 = (i & 31) * 4;
                *(float4*)&As[row * 132 + c4] =
                    *(const float4*)(g_hist + (m0 + row) * HID + kc * 128 + c4);
            }
            __syncthreads();
            const unsigned long long* wp = wpk + (size_t)kc * 64 * 32 + half * 16;
            const float* ar = As + r * 132;
#pragma unroll 8
            for (int k2 = 0; k2 < 64; k2++) {
                unsigned long long hp = pk2(ar[2 * k2], ar[2 * k2 + 1]);
                const unsigned long long* w = wp + (size_t)k2 * 32;
#pragma unroll
                for (int c = 0; c < 8; c++) fma2(acc2[c], hp, w[c * 2 + 1]);
            }
        }
#pragma unroll
        for (int c = 0; c < 8; c++) {
            float2 u = unpk(acc2[c]);
            int col = half * 16 + 2 * c + 1;
            out[(m0 + r) * OUTSZ + col] = u.x + u.y + sbout[col];
        }
    }
}

// ---------------------------------------------------------------------------
extern "C" void kernel_launch(void* const* d_in, const int* in_sizes, int n_in,
                              void* d_out, int out_size)
{
    const float* inputs = (const float*)d_in[0];
    const float* Wrec   = (const float*)d_in[1];
    const float* Win    = (const float*)d_in[2];
    const float* brec   = (const float*)d_in[3];
    const float* Wout   = (const float*)d_in[4];
    const float* bout   = (const float*)d_in[5];
    float* out = (float*)d_out;

    const int smem1 = (128 * 132 + 128 * 128) * 4;   // 133120
    cudaFuncSetAttribute(xproj_kernel, cudaFuncAttributeMaxDynamicSharedMemorySize, smem1);
    cudaFuncSetAttribute(rnn_kernel,   cudaFuncAttributeMaxDynamicSharedMemorySize, SM2_BYTES);
    cudaFuncSetAttribute(ogemm_kernel, cudaFuncAttributeMaxDynamicSharedMemorySize, OG_BYTES);

    dim3 g1((TSTEPS * BATCH) / 128, HID / 128);
    xproj_kernel<<<g1, 256, smem1>>>(inputs, Win, brec);

    rnn_kernel<<<128, THR2, SM2_BYTES>>>(Wrec);

    ogemm_kernel<<<(TSTEPS * BATCH) / 128, 256, OG_BYTES>>>(Wout, bout, out);

    (void)in_sizes; (void)n_in; (void)out_size;
}